// round 6
// baseline (speedup 1.0000x reference)
#include <cuda_runtime.h>
#include <cstdint>

// Problem constants (fixed by the dataset: V=8192 vertices, E=40000 tets)
#define V 8192
#define E 40000
#define E_BLOCKS ((E + 255) / 256)

// Scratch (device globals — no allocations allowed). 16B-aligned for float4 LDG.
__device__ __align__(16) float g_dx[V];
__device__ __align__(16) float g_dy[V];
__device__ __align__(16) float g_dz[V];
__device__ float g_kin_partial[V];       // one per matrix row
__device__ float g_el_partial[E_BLOCKS]; // one per elastic block

// ---------------------------------------------------------------------------
// Kernel 1: delta = next_position - (position + velocity*dt + ext_acc*dt^2)
// stored SoA so the matvec can do float4 loads.
// ---------------------------------------------------------------------------
__global__ void delta_kernel(const float* __restrict__ next_pos,
                             const float* __restrict__ pos,
                             const float* __restrict__ vel,
                             const float* __restrict__ ext,
                             const float* __restrict__ ts_ptr)
{
    int v = blockIdx.x * blockDim.x + threadIdx.x;
    if (v >= V) return;
    float dt  = ts_ptr[0];
    float dt2 = dt * dt;
    int b = v * 3;
    g_dx[v] = next_pos[b + 0] - (pos[b + 0] + vel[b + 0] * dt + ext[b + 0] * dt2);
    g_dy[v] = next_pos[b + 1] - (pos[b + 1] + vel[b + 1] * dt + ext[b + 1] * dt2);
    g_dz[v] = next_pos[b + 2] - (pos[b + 2] + vel[b + 2] * dt + ext[b + 2] * dt2);
}

// ---------------------------------------------------------------------------
// Kernel 2: per-row fused matvec + dot.
// Block i computes s_c = sum_j M[i][j] * delta_c[j]  (c = x,y,z),
// then g_kin_partial[i] = delta_x[i]*s_x + delta_y[i]*s_y + delta_z[i]*s_z.
// M row read is the only DRAM traffic (32 KB/row, 268 MB total).
// ---------------------------------------------------------------------------
__global__ __launch_bounds__(256) void matvec_kernel(const float* __restrict__ M)
{
    const int row = blockIdx.x;
    const float4* __restrict__ Mrow = reinterpret_cast<const float4*>(M + (size_t)row * V);
    const float4* __restrict__ DX = reinterpret_cast<const float4*>(g_dx);
    const float4* __restrict__ DY = reinterpret_cast<const float4*>(g_dy);
    const float4* __restrict__ DZ = reinterpret_cast<const float4*>(g_dz);

    float s0 = 0.f, s1 = 0.f, s2 = 0.f;
#pragma unroll
    for (int it = 0; it < (V / 4) / 256; ++it) {
        int idx = threadIdx.x + it * 256;
        float4 m = Mrow[idx];
        float4 x = DX[idx];
        float4 y = DY[idx];
        float4 z = DZ[idx];
        s0 += m.x * x.x + m.y * x.y + m.z * x.z + m.w * x.w;
        s1 += m.x * y.x + m.y * y.y + m.z * y.z + m.w * y.w;
        s2 += m.x * z.x + m.y * z.y + m.z * z.z + m.w * z.w;
    }

    // warp reduce
#pragma unroll
    for (int off = 16; off > 0; off >>= 1) {
        s0 += __shfl_down_sync(0xFFFFFFFFu, s0, off);
        s1 += __shfl_down_sync(0xFFFFFFFFu, s1, off);
        s2 += __shfl_down_sync(0xFFFFFFFFu, s2, off);
    }
    __shared__ float sh[3][8];
    int lane = threadIdx.x & 31;
    int warp = threadIdx.x >> 5;
    if (lane == 0) { sh[0][warp] = s0; sh[1][warp] = s1; sh[2][warp] = s2; }
    __syncthreads();
    if (threadIdx.x == 0) {
        float S0 = 0.f, S1 = 0.f, S2 = 0.f;
#pragma unroll
        for (int w = 0; w < 8; ++w) { S0 += sh[0][w]; S1 += sh[1][w]; S2 += sh[2][w]; }
        g_kin_partial[row] = g_dx[row] * S0 + g_dy[row] * S1 + g_dz[row] * S2;
    }
}

// ---------------------------------------------------------------------------
// Kernel 3: elastic energy per element, block-reduced into g_el_partial.
//   F[t][l] = sum_f next_pos[elem[e][f]][t] * poly[e][f][l]   (l < 3)
//   Ic = trace(F^T F) = sum F_ij^2 ; J = det(F)
//   alpha = 0.75*mu/lam + 1 ; Ic_v = relu(Ic + 1)
//   psi = mu/2*(Ic-3) + lam/2*(J-alpha)^2 - mu/2*log(Ic_v + 1e-30)
//   contribution = psi * measure[e][3][0]
//
// NOTE: elements is int32 on device (JAX silently downcasts int64 without
// the x64 flag). Indices clamped defensively so a dtype surprise shows up as
// rel_err, not an illegal access.
// ---------------------------------------------------------------------------
__global__ __launch_bounds__(256) void elastic_kernel(
    const float* __restrict__ next_pos,
    const int* __restrict__ elems,
    const float* __restrict__ poly,
    const float* __restrict__ measure,
    const float* __restrict__ lam,
    const float* __restrict__ mu)
{
    int e = blockIdx.x * blockDim.x + threadIdx.x;
    float val = 0.f;
    if (e < E) {
        float F00 = 0.f, F01 = 0.f, F02 = 0.f;
        float F10 = 0.f, F11 = 0.f, F12 = 0.f;
        float F20 = 0.f, F21 = 0.f, F22 = 0.f;
        const int4 ev = reinterpret_cast<const int4*>(elems)[e];
        int vidx[4] = { ev.x, ev.y, ev.z, ev.w };
        const float4* __restrict__ pl4 = reinterpret_cast<const float4*>(poly) + (size_t)e * 4;
#pragma unroll
        for (int f = 0; f < 4; ++f) {
            int vi = vidx[f];
            vi = vi < 0 ? 0 : (vi >= V ? V - 1 : vi);   // defensive clamp
            const float* p = next_pos + (size_t)vi * 3;
            float px = p[0], py = p[1], pz = p[2];
            float4 pl = pl4[f];
            float p0 = pl.x, p1 = pl.y, p2 = pl.z;
            F00 += px * p0; F01 += px * p1; F02 += px * p2;
            F10 += py * p0; F11 += py * p1; F12 += py * p2;
            F20 += pz * p0; F21 += pz * p1; F22 += pz * p2;
        }
        float Ic = F00*F00 + F01*F01 + F02*F02
                 + F10*F10 + F11*F11 + F12*F12
                 + F20*F20 + F21*F21 + F22*F22;
        float J = F00 * (F11 * F22 - F12 * F21)
                - F01 * (F10 * F22 - F12 * F20)
                + F02 * (F10 * F21 - F11 * F20);
        float l = lam[e], m = mu[e];
        float alpha = 0.75f * m / l + 1.0f;
        float Icv = fmaxf(Ic + 1.0f, 0.0f);
        float d = J - alpha;
        float psi = 0.5f * m * (Ic - 3.0f)
                  + 0.5f * l * d * d
                  - 0.5f * m * logf(Icv + 1e-30f);
        val = psi * measure[(size_t)e * 4 + 3];
    }

    // block reduce
#pragma unroll
    for (int off = 16; off > 0; off >>= 1)
        val += __shfl_down_sync(0xFFFFFFFFu, val, off);
    __shared__ float sh[8];
    int lane = threadIdx.x & 31;
    int warp = threadIdx.x >> 5;
    if (lane == 0) sh[warp] = val;
    __syncthreads();
    if (threadIdx.x == 0) {
        float s = 0.f;
#pragma unroll
        for (int w = 0; w < 8; ++w) s += sh[w];
        g_el_partial[blockIdx.x] = s;
    }
}

// ---------------------------------------------------------------------------
// Kernel 4: final reduction (double accumulation), writes [energy, kin, el].
// ---------------------------------------------------------------------------
__global__ __launch_bounds__(256) void final_kernel(const float* __restrict__ ts_ptr,
                                                    float* __restrict__ out)
{
    __shared__ double shk[8], she[8];
    double ksum = 0.0, esum = 0.0;
    for (int i = threadIdx.x; i < V; i += 256) ksum += (double)g_kin_partial[i];
    for (int i = threadIdx.x; i < E_BLOCKS; i += 256) esum += (double)g_el_partial[i];
#pragma unroll
    for (int off = 16; off > 0; off >>= 1) {
        ksum += __shfl_down_sync(0xFFFFFFFFu, ksum, off);
        esum += __shfl_down_sync(0xFFFFFFFFu, esum, off);
    }
    int lane = threadIdx.x & 31;
    int warp = threadIdx.x >> 5;
    if (lane == 0) { shk[warp] = ksum; she[warp] = esum; }
    __syncthreads();
    if (threadIdx.x == 0) {
        double K = 0.0, Eacc = 0.0;
#pragma unroll
        for (int w = 0; w < 8; ++w) { K += shk[w]; Eacc += she[w]; }
        double dt = (double)ts_ptr[0];
        double inv_h = 1.0 / dt;
        double coeff = inv_h * inv_h * 0.5;
        double kin = coeff * K;
        out[0] = (float)(kin + Eacc);
        out[1] = (float)kin;
        out[2] = (float)Eacc;
    }
}

// ---------------------------------------------------------------------------
// Launch
// ---------------------------------------------------------------------------
extern "C" void kernel_launch(void* const* d_in, const int* in_sizes, int n_in,
                              void* d_out, int out_size)
{
    const float* next_pos = (const float*)d_in[0];
    const float* pos      = (const float*)d_in[1];
    const float* vel      = (const float*)d_in[2];
    const float* ext      = (const float*)d_in[3];
    const float* M        = (const float*)d_in[4];
    const int*   elems    = (const int*)d_in[5];
    const float* poly     = (const float*)d_in[6];
    const float* measure  = (const float*)d_in[7];
    const float* lam      = (const float*)d_in[8];
    const float* mu       = (const float*)d_in[9];
    const float* ts       = (const float*)d_in[10];
    float* out = (float*)d_out;

    delta_kernel<<<(V + 255) / 256, 256>>>(next_pos, pos, vel, ext, ts);
    elastic_kernel<<<E_BLOCKS, 256>>>(next_pos, elems, poly, measure, lam, mu);
    matvec_kernel<<<V, 256>>>(M);
    final_kernel<<<1, 256>>>(ts, out);
}